// round 17
// baseline (speedup 1.0000x reference)
#include <cuda_runtime.h>
#include <cuda_fp16.h>
#include <cstdint>
#include <cstddef>

#define NN   20000
#define EE   320000
#define HH   8
#define FUNI 256
#define FOUT 64
#define HF   512   // H*FOUT
#define MSG_SCALE 64.0f
#define INV_MSG_SCALE (1.0f / 64.0f)

// ---------------- scratch (device globals; no runtime allocation) ----------------
__device__ uint32_t g_embP[2][NN * 64];          // packed emb [N][64u] (128 bf16)
__device__ uint32_t g_Wpk[2][128 * 128];         // packed W [128][128u] (256 bf16)
__device__ uint32_t g_Wc[2][512 * 64];           // combined layer-0 weight [512][64u]
__device__ uint32_t g_Bp0[2][512 * 128];         // layer-0 weights [512][128u]
__device__ uint32_t g_Bp1[2][512 * 256];         // layer-1 weights [512][256u]
__device__ uint32_t g_hpd[2][NN * 128];          // projected features, e4m3 x64-scaled [N][128u]
__device__ uint32_t g_x0d[2][NN * HF / 2];       // layer-0 aggregated (bf16, ELU'd)
__device__ float g_mean[2][NN * FOUT];           // layer-1 head-mean output (fp32)
__device__ float g_sd[2][NN * HH];
__device__ float g_td[2][NN * HH];
__device__ float g_fa[FOUT];

// CSR scratch (per type)
__device__ int g_cntd[2][NN];
__device__ int g_rowptr[2][NN + 1];
__device__ int g_woffd[2][NN];
__device__ int g_csr[2][EE];

// ---------------- static stream/event context (created at load, NOT during capture) ----
struct HxCtx {
    cudaStream_t s1, s2, s3;
    cudaEvent_t e0, e1, ec0, ec1, ep0, ep1;
    HxCtx() {
        cudaStreamCreateWithFlags(&s1, cudaStreamNonBlocking);
        cudaStreamCreateWithFlags(&s2, cudaStreamNonBlocking);
        cudaStreamCreateWithFlags(&s3, cudaStreamNonBlocking);
        cudaEventCreateWithFlags(&e0, cudaEventDisableTiming);
        cudaEventCreateWithFlags(&e1, cudaEventDisableTiming);
        cudaEventCreateWithFlags(&ec0, cudaEventDisableTiming);
        cudaEventCreateWithFlags(&ec1, cudaEventDisableTiming);
        cudaEventCreateWithFlags(&ep0, cudaEventDisableTiming);
        cudaEventCreateWithFlags(&ep1, cudaEventDisableTiming);
    }
};
static HxCtx g_hx;

// ---------------- helpers ----------------
__device__ __forceinline__ uint32_t smem_to_u32(const void* p) {
    uint32_t a;
    asm("{ .reg .u64 t; cvta.to.shared.u64 t, %1; cvt.u32.u64 %0, t; }" : "=r"(a) : "l"(p));
    return a;
}
__device__ __forceinline__ void cp16(uint32_t saddr, const void* g) {
    asm volatile("cp.async.cg.shared.global [%0], [%1], 16;" :: "r"(saddr), "l"(g));
}
__device__ __forceinline__ void sts_zero16(uint32_t saddr) {
    asm volatile("st.shared.v4.b32 [%0], {%1,%1,%1,%1};" :: "r"(saddr), "r"(0u));
}
#define CP_COMMIT() asm volatile("cp.async.commit_group;" ::: "memory")
#define CP_WAIT2()  asm volatile("cp.async.wait_group 2;" ::: "memory")

__device__ __forceinline__ uint32_t pack_bf16x2(float a, float b) {
    uint32_t r;
    asm("cvt.rn.bf16x2.f32 %0, %1, %2;" : "=r"(r) : "f"(b), "f"(a));
    return r;
}
__device__ __forceinline__ uint16_t pack_e4m3x2(float a, float b) {   // lo=a, hi=b
    uint16_t r;
    asm("cvt.rn.satfinite.e4m3x2.f32 %0, %1, %2;" : "=h"(r) : "f"(b), "f"(a));
    return r;
}
__device__ __forceinline__ float2 e4m3x2_to_f2(uint16_t u) {
    uint32_t h2;
    asm("cvt.rn.f16x2.e4m3x2 %0, %1;" : "=r"(h2) : "h"(u));
    __half2 hh = *reinterpret_cast<__half2*>(&h2);
    return __half22float2(hh);
}
__device__ __forceinline__ float bf_lo(uint32_t u) { return __uint_as_float(u << 16); }
__device__ __forceinline__ float bf_hi(uint32_t u) { return __uint_as_float(u & 0xffff0000u); }
__device__ __forceinline__ float eluf(float x) { return x > 0.f ? x : (__expf(x) - 1.f); }

__device__ __forceinline__ void mma_bf16(float* c, const uint32_t* a, const uint32_t* b) {
    asm volatile("mma.sync.aligned.m16n8k16.row.col.f32.bf16.bf16.f32 "
                 "{%0,%1,%2,%3}, {%4,%5,%6,%7}, {%8,%9}, {%0,%1,%2,%3};"
                 : "+f"(c[0]), "+f"(c[1]), "+f"(c[2]), "+f"(c[3])
                 : "r"(a[0]), "r"(a[1]), "r"(a[2]), "r"(a[3]), "r"(b[0]), "r"(b[1]));
}

// ---------------- bf16 mma GEMM + fused s/t epilogue ----------------
// If sOut != nullptr: C is written as e4m3 (x64 scale) [M][NC/2 u16] and the
// s/t projections are emitted from the fp32 accumulators. Otherwise C is bf16x2.
#define STAGES  3
#define STRIDEU 20
#define TILEU   (128 * STRIDEU)
#define STAGEU  (2 * TILEU)
#define SMEM_GEMM (STAGES * STAGEU * 4)    // 61440 bytes

__global__ __launch_bounds__(256, 2)
void gemm_bf16(const uint32_t* __restrict__ A, const uint32_t* __restrict__ Bt,
               uint32_t* __restrict__ C, int M, int K, int NC,
               const float* __restrict__ asrc, const float* __restrict__ atrg,
               float* __restrict__ sOut, float* __restrict__ tOut)
{
    const uint32_t FULL = 0xffffffffu;
    extern __shared__ uint32_t smu[];
    const int tid  = threadIdx.x;
    const int wid  = tid >> 5, lane = tid & 31;
    const int g    = lane >> 2, t = lane & 3;
    const int bm   = blockIdx.y << 7, bn = blockIdx.x << 7;
    const int m0   = (wid >> 1) * 32;
    const int n0   = (wid & 1) * 64;
    const int KU   = K >> 1;
    const int NCU  = NC >> 1;
    const int P    = K >> 5;

    const uint32_t sb = smem_to_u32(smu);
    const int lrow = tid >> 2;
    const int lc4  = tid & 3;

    float acc[2][8][4];
#pragma unroll
    for (int i = 0; i < 2; i++)
#pragma unroll
        for (int j = 0; j < 8; j++)
#pragma unroll
            for (int q = 0; q < 4; q++) acc[i][j][q] = 0.f;

#pragma unroll
    for (int s = 0; s < STAGES; s++) {
        uint32_t stb = sb + s * STAGEU * 4;
#pragma unroll
        for (int j = 0; j < 2; j++) {
            int row = lrow + j * 64;
            uint32_t sa = stb + (row * STRIDEU + lc4 * 4) * 4;
            int ar = bm + row;
            if (ar < M) cp16(sa, A + (size_t)ar * KU + s * 16 + lc4 * 4);
            else        sts_zero16(sa);
            uint32_t sbB = stb + TILEU * 4 + (row * STRIDEU + lc4 * 4) * 4;
            cp16(sbB, Bt + (size_t)(bn + row) * KU + s * 16 + lc4 * 4);
        }
        CP_COMMIT();
    }

    for (int p = 0; p < P; p++) {
        const int slot = p % STAGES;
        CP_WAIT2();
        __syncthreads();
        const uint32_t* As = smu + slot * STAGEU;
        const uint32_t* Bs = As + TILEU;

#pragma unroll
        for (int ks = 0; ks < 2; ks++) {
            uint32_t a[2][4], b[8][2];
#pragma unroll
            for (int i = 0; i < 2; i++) {
                int base = (m0 + i * 16 + g) * STRIDEU + ks * 8 + t;
                a[i][0] = As[base];
                a[i][1] = As[base + 8 * STRIDEU];
                a[i][2] = As[base + 4];
                a[i][3] = As[base + 8 * STRIDEU + 4];
            }
#pragma unroll
            for (int j = 0; j < 8; j++) {
                int bb = (n0 + j * 8 + g) * STRIDEU + ks * 8 + t;
                b[j][0] = Bs[bb];
                b[j][1] = Bs[bb + 4];
            }
#pragma unroll
            for (int i = 0; i < 2; i++)
#pragma unroll
                for (int j = 0; j < 8; j++)
                    mma_bf16(acc[i][j], a[i], b[j]);
        }
        __syncthreads();

        int np = p + STAGES;
        if (np < P) {
            uint32_t stb = sb + slot * STAGEU * 4;
#pragma unroll
            for (int j = 0; j < 2; j++) {
                int row = lrow + j * 64;
                uint32_t sa = stb + (row * STRIDEU + lc4 * 4) * 4;
                int ar = bm + row;
                if (ar < M) cp16(sa, A + (size_t)ar * KU + np * 16 + lc4 * 4);
                else        sts_zero16(sa);
                uint32_t sbB = stb + TILEU * 4 + (row * STRIDEU + lc4 * 4) * 4;
                cp16(sbB, Bt + (size_t)(bn + row) * KU + np * 16 + lc4 * 4);
            }
        }
        CP_COMMIT();
    }

    if (sOut == nullptr) {
        // ---- bf16x2 C store (weight-combine path) ----
#pragma unroll
        for (int i = 0; i < 2; i++) {
            int r0 = bm + m0 + i * 16 + g;
#pragma unroll
            for (int j = 0; j < 8; j++) {
                int colu = ((bn + n0 + j * 8) >> 1) + t;
                if (r0 < M)
                    C[(size_t)r0 * NCU + colu] = pack_bf16x2(acc[i][j][0], acc[i][j][1]);
                if (r0 + 8 < M)
                    C[(size_t)(r0 + 8) * NCU + colu] = pack_bf16x2(acc[i][j][2], acc[i][j][3]);
            }
        }
        return;
    }

    // ---- e4m3 (x64) C store: row = NC/2 u16 ----
    {
        uint16_t* C16 = (uint16_t*)C;
#pragma unroll
        for (int i = 0; i < 2; i++) {
            int r0 = bm + m0 + i * 16 + g;
#pragma unroll
            for (int j = 0; j < 8; j++) {
                int colh = ((bn + n0 + j * 8) >> 1) + t;   // u16 index (2 fp8 each)
                if (r0 < M)
                    C16[(size_t)r0 * NCU + colh] =
                        pack_e4m3x2(acc[i][j][0] * MSG_SCALE, acc[i][j][1] * MSG_SCALE);
                if (r0 + 8 < M)
                    C16[(size_t)(r0 + 8) * NCU + colh] =
                        pack_e4m3x2(acc[i][j][2] * MSG_SCALE, acc[i][j][3] * MSG_SCALE);
            }
        }
    }

    // ---- fused s/t projection (warp's 64 cols = exactly one head) ----
    {
        int hh = (bn + n0) >> 6;
        const float* av = asrc + hh * 64;
        const float* bv = atrg + hh * 64;
        float aw[16], bw[16];
#pragma unroll
        for (int j = 0; j < 8; j++) {
            int c0 = j * 8 + 2 * t;
            aw[2 * j] = av[c0];     aw[2 * j + 1] = av[c0 + 1];
            bw[2 * j] = bv[c0];     bw[2 * j + 1] = bv[c0 + 1];
        }
#pragma unroll
        for (int i = 0; i < 2; i++) {
#pragma unroll
            for (int half = 0; half < 2; half++) {
                float ss = 0.f, ts = 0.f;
#pragma unroll
                for (int j = 0; j < 8; j++) {
                    float c0 = acc[i][j][half * 2 + 0];
                    float c1 = acc[i][j][half * 2 + 1];
                    ss += c0 * aw[2 * j] + c1 * aw[2 * j + 1];
                    ts += c0 * bw[2 * j] + c1 * bw[2 * j + 1];
                }
                ss += __shfl_xor_sync(FULL, ss, 1);
                ss += __shfl_xor_sync(FULL, ss, 2);
                ts += __shfl_xor_sync(FULL, ts, 1);
                ts += __shfl_xor_sync(FULL, ts, 2);
                int row = bm + m0 + i * 16 + g + half * 8;
                if (t == 0 && row < M) {
                    sOut[row * 8 + hh] = ss;
                    tOut[row * 8 + hh] = ts;
                }
            }
        }
    }
}

// ---------------- CSR build (per type t) ----------------
__global__ void zero_cnt(int t) {
    int i = blockIdx.x * blockDim.x + threadIdx.x;
    if (i < NN) g_cntd[t][i] = 0;
}
__global__ void hist_kernel(const int* __restrict__ trg, int t) {
    int e = blockIdx.x * blockDim.x + threadIdx.x;
    if (e < EE) atomicAdd(&g_cntd[t][trg[e]], 1);
}
#define SCAN_CH 20
__global__ __launch_bounds__(1024) void scan_kernel(int t) {
    __shared__ int part[1024];
    int tid = threadIdx.x;
    int base = tid * SCAN_CH;
    int loc[SCAN_CH];
    int s = 0;
#pragma unroll
    for (int i = 0; i < SCAN_CH; i++) {
        int idx = base + i;
        int v = (idx < NN) ? g_cntd[t][idx] : 0;
        loc[i] = s;
        s += v;
    }
    part[tid] = s;
    __syncthreads();
    for (int d = 1; d < 1024; d <<= 1) {
        int v = (tid >= d) ? part[tid - d] : 0;
        __syncthreads();
        part[tid] += v;
        __syncthreads();
    }
    int excl = part[tid] - s;
#pragma unroll
    for (int i = 0; i < SCAN_CH; i++) {
        int idx = base + i;
        if (idx < NN) {
            int v = loc[i] + excl;
            g_rowptr[t][idx] = v;
            g_woffd[t][idx] = v;
        }
    }
    if (tid == 1023) g_rowptr[t][NN] = part[1023];
}
__global__ void fill_kernel(const int* __restrict__ src, const int* __restrict__ trg, int t) {
    int e = blockIdx.x * blockDim.x + threadIdx.x;
    if (e >= EE) return;
    int p = atomicAdd(&g_woffd[t][trg[e]], 1);
    g_csr[t][p] = src[e];
}

// ---------------- gather-aggregate: one warp per node, fp8 messages ----------------
// hp rows: 512 e4m3 (x64 scale) = 128 u32. Each lane covers 16 values (head = lane>>2).
// mode 1: ELU + bf16-packed out [N][256u].  mode 2: head-mean fp32 out [N][64].
__global__ __launch_bounds__(256) void gather_agg(const int* __restrict__ csr,
                                                  const int* __restrict__ rowptr,
                                                  const uint32_t* __restrict__ hp,
                                                  const float* __restrict__ sArr,
                                                  const float* __restrict__ tArr,
                                                  void* __restrict__ outp,
                                                  int mode)
{
    const uint32_t FULL = 0xffffffffu;
    int node = (blockIdx.x * 256 + threadIdx.x) >> 5;
    int lane = threadIdx.x & 31;
    if (node >= NN) return;
    int beg = rowptr[node], end = rowptr[node + 1];

    const int h = lane & 7;          // head for the s/exp phase
    const int eg = lane >> 3;        // edge-in-group (0..3)
    const int mh = lane >> 2;        // head owned in the message layout
    float tval = tArr[node * 8 + h];

    float dsum = 0.f;
    float acc[16];
#pragma unroll
    for (int k = 0; k < 16; k++) acc[k] = 0.f;

    for (int base = beg; base < end; base += 32) {
        int nrem = end - base; if (nrem > 32) nrem = 32;
        int sv = (base + lane < end) ? csr[base + lane] : 0;

        for (int i4 = 0; i4 < nrem; i4 += 4) {
            int myEdge = i4 + eg;
            int srcE = __shfl_sync(FULL, sv, myEdge & 31);
            float ex = 0.f;
            if (myEdge < nrem) {
                float v = sArr[srcE * 8 + h] + tval;
                ex = __expf(fmaxf(v, 0.2f * v));   // global max-shift cancels in alpha
                dsum += ex;
            }
#pragma unroll
            for (int i = 0; i < 4; i++) {
                int srcp = __shfl_sync(FULL, sv, (i4 + i) & 31);
                float al = __shfl_sync(FULL, ex, (i << 3) | mh);
                uint4 v = ((const uint4*)(hp + (size_t)srcp * 128))[lane];
#pragma unroll
                for (int w = 0; w < 4; w++) {
                    uint32_t u = (w == 0) ? v.x : (w == 1) ? v.y : (w == 2) ? v.z : v.w;
                    float2 f0 = e4m3x2_to_f2((uint16_t)(u & 0xffffu));
                    float2 f1 = e4m3x2_to_f2((uint16_t)(u >> 16));
                    acc[4 * w + 0] += al * f0.x;
                    acc[4 * w + 1] += al * f0.y;
                    acc[4 * w + 2] += al * f1.x;
                    acc[4 * w + 3] += al * f1.y;
                }
            }
        }
    }

    // per-head denominators: after xor-8/16, lane L holds denom for head L&7
    dsum += __shfl_xor_sync(FULL, dsum, 8);
    dsum += __shfl_xor_sync(FULL, dsum, 16);
    float dn = __shfl_sync(FULL, dsum, mh);
    float inv = 1.f / ((dn + 1e-16f) * MSG_SCALE);

    if (mode == 1) {
        uint32_t* out = (uint32_t*)outp;
        uint4* ob = (uint4*)(out + (size_t)node * 256 + lane * 8);
        uint4 p0, p1;
        p0.x = pack_bf16x2(eluf(acc[0] * inv),  eluf(acc[1] * inv));
        p0.y = pack_bf16x2(eluf(acc[2] * inv),  eluf(acc[3] * inv));
        p0.z = pack_bf16x2(eluf(acc[4] * inv),  eluf(acc[5] * inv));
        p0.w = pack_bf16x2(eluf(acc[6] * inv),  eluf(acc[7] * inv));
        p1.x = pack_bf16x2(eluf(acc[8] * inv),  eluf(acc[9] * inv));
        p1.y = pack_bf16x2(eluf(acc[10] * inv), eluf(acc[11] * inv));
        p1.z = pack_bf16x2(eluf(acc[12] * inv), eluf(acc[13] * inv));
        p1.w = pack_bf16x2(eluf(acc[14] * inv), eluf(acc[15] * inv));
        ob[0] = p0;
        ob[1] = p1;
    } else {
        // head-mean: lanes sharing lane&3 cover all 8 heads for the same 16-dim span
        float m[16];
#pragma unroll
        for (int k = 0; k < 16; k++) {
            m[k] = acc[k] * inv;
            m[k] += __shfl_xor_sync(FULL, m[k], 4);
            m[k] += __shfl_xor_sync(FULL, m[k], 8);
            m[k] += __shfl_xor_sync(FULL, m[k], 16);
        }
        if (lane < 4) {
            float4* out = (float4*)((float*)outp + (size_t)node * 64 + lane * 16);
#pragma unroll
            for (int q = 0; q < 4; q++)
                out[q] = make_float4(m[4 * q] * 0.125f, m[4 * q + 1] * 0.125f,
                                     m[4 * q + 2] * 0.125f, m[4 * q + 3] * 0.125f);
        }
    }
}

// ---------------- prep kernels ----------------
__global__ void pack_bf16_k(uint32_t* __restrict__ dst, const float* __restrict__ src, int n2) {
    int i = blockIdx.x * blockDim.x + threadIdx.x;
    if (i < n2) dst[i] = pack_bf16x2(src[2 * i], src[2 * i + 1]);
}
__global__ void repack_pack(uint32_t* __restrict__ Bt, const float* __restrict__ w, int fin) {
    int finu = fin >> 1;
    int i = blockIdx.x * blockDim.x + threadIdx.x;
    if (i >= 512 * finu) return;
    int n = i / finu, ku = i % finu;
    int h = n >> 6, o = n & 63;
    int k0 = 2 * ku;
    Bt[i] = pack_bf16x2(w[((size_t)(h * fin + k0) << 6) + o],
                        w[((size_t)(h * fin + k0 + 1) << 6) + o]);
}

// fa[o] = (hemb1[0,:] @ W1) @ aw1[:,o], all fp32 from raw inputs
__global__ __launch_bounds__(64) void fa_kernel(const float* __restrict__ hemb1,
                                                const float* __restrict__ W1,
                                                const float* __restrict__ aw1) {
    __shared__ float tr[256];
    int o = threadIdx.x;
    for (int f = o; f < 256; f += 64) {
        float a = 0.f;
        for (int k = 0; k < 128; k++) a += hemb1[k] * W1[k * 256 + f];
        tr[f] = a;
    }
    __syncthreads();
    float a = 0.f;
    for (int f = 0; f < 256; f++) a += tr[f] * aw1[f * 64 + o];
    g_fa[o] = a;
}

__global__ __launch_bounds__(64) void final_kernel(const float* __restrict__ aw2,
                                                   const float* __restrict__ am,
                                                   const float* __restrict__ fcw,
                                                   const float* __restrict__ fcb,
                                                   float* __restrict__ out) {
    __shared__ float ta[2][64];
    __shared__ float r0[64], r1[64];
    __shared__ float sc[2];
    int n = blockIdx.x, o = threadIdx.x;

    float m0 = g_mean[0][(size_t)n * 64 + o];
    float m1 = g_mean[1][(size_t)n * 64 + o];
    ta[0][o] = m0; ta[1][o] = m1;
    __syncthreads();

    float amo = am[o];
    float fa = g_fa[o];
    {
        float acc0 = fa, acc1 = fa;
        for (int d = 0; d < 64; d++) {
            float w = aw2[d * 64 + o];
            acc0 += ta[0][d] * w;
            acc1 += ta[1][d] * w;
        }
        r0[o] = tanhf(acc0) * amo;
        r1[o] = tanhf(acc1) * amo;
    }
    __syncthreads();
    if (o == 0) {
        float s0 = 0.f, s1 = 0.f;
        for (int d = 0; d < 64; d++) { s0 += r0[d]; s1 += r1[d]; }
        sc[0] = s0; sc[1] = s1;
    }
    __syncthreads();
    float mx = fmaxf(sc[0], sc[1]);
    float b0 = __expf(sc[0] - mx), b1 = __expf(sc[1] - mx);
    float inv = 1.f / (b0 + b1);
    b0 *= inv; b1 *= inv;
    float fus = b0 * m0 + b1 * m1;

    r0[o] = m0 * fcw[o * 2 + 0] + m1 * fcw[(64 + o) * 2 + 0] + fus * fcw[(128 + o) * 2 + 0];
    r1[o] = m0 * fcw[o * 2 + 1] + m1 * fcw[(64 + o) * 2 + 1] + fus * fcw[(128 + o) * 2 + 1];
    __syncthreads();
    if (o == 0) {
        float l0 = fcb[0], l1 = fcb[1];
        for (int d = 0; d < 64; d++) { l0 += r0[d]; l1 += r1[d]; }
        float m = fmaxf(l0, l1);
        float lse = m + logf(__expf(l0 - m) + __expf(l1 - m));
        out[n * 2 + 0] = l0 - lse;
        out[n * 2 + 1] = l1 - lse;
    }
}

// ---------------- launcher: fork/join, all prep + CSR + weight-combine on side streams ----
extern "C" void kernel_launch(void* const* d_in, const int* in_sizes, int n_in,
                              void* d_out, int out_size)
{
    const float* hemb[2] = {(const float*)d_in[0], (const float*)d_in[1]};
    const float* W[2]    = {(const float*)d_in[2], (const float*)d_in[3]};
    const float* gw[2][2]    = {{(const float*)d_in[4],  (const float*)d_in[7]},
                                {(const float*)d_in[10], (const float*)d_in[13]}};
    const float* gasrc[2][2] = {{(const float*)d_in[5],  (const float*)d_in[8]},
                                {(const float*)d_in[11], (const float*)d_in[14]}};
    const float* gatrg[2][2] = {{(const float*)d_in[6],  (const float*)d_in[9]},
                                {(const float*)d_in[12], (const float*)d_in[15]}};
    const float* aw1 = (const float*)d_in[16];
    const float* aw2 = (const float*)d_in[17];
    const float* am  = (const float*)d_in[18];
    const float* fcw = (const float*)d_in[19];
    const float* fcb = (const float*)d_in[20];
    const int* edge[2] = {(const int*)d_in[21], (const int*)d_in[22]};

    uint32_t *embP[2], *Wpk[2], *Wc[2], *Bp0[2], *Bp1[2], *hp[2], *x0[2];
    float *meanArr[2], *sArr[2], *tArr[2];
    int *csr[2], *rowptr[2];
    {
        uint32_t* ub;
        cudaGetSymbolAddress((void**)&ub, g_embP);  embP[0] = ub;  embP[1] = ub + NN * 64;
        cudaGetSymbolAddress((void**)&ub, g_Wpk);   Wpk[0] = ub;   Wpk[1] = ub + 128 * 128;
        cudaGetSymbolAddress((void**)&ub, g_Wc);    Wc[0] = ub;    Wc[1] = ub + 512 * 64;
        cudaGetSymbolAddress((void**)&ub, g_Bp0);   Bp0[0] = ub;   Bp0[1] = ub + 512 * 128;
        cudaGetSymbolAddress((void**)&ub, g_Bp1);   Bp1[0] = ub;   Bp1[1] = ub + 512 * 256;
        cudaGetSymbolAddress((void**)&ub, g_hpd);   hp[0] = ub;    hp[1] = ub + NN * 128;
        cudaGetSymbolAddress((void**)&ub, g_x0d);   x0[0] = ub;    x0[1] = ub + NN * HF / 2;
        float* fb;
        cudaGetSymbolAddress((void**)&fb, g_mean);  meanArr[0] = fb; meanArr[1] = fb + NN * FOUT;
        cudaGetSymbolAddress((void**)&fb, g_sd);    sArr[0] = fb;  sArr[1] = fb + NN * HH;
        cudaGetSymbolAddress((void**)&fb, g_td);    tArr[0] = fb;  tArr[1] = fb + NN * HH;
        int* ib;
        cudaGetSymbolAddress((void**)&ib, g_csr);    csr[0] = ib;    csr[1] = ib + EE;
        cudaGetSymbolAddress((void**)&ib, g_rowptr); rowptr[0] = ib; rowptr[1] = ib + (NN + 1);
    }

    cudaFuncSetAttribute(gemm_bf16, cudaFuncAttributeMaxDynamicSharedMemorySize, SMEM_GEMM);

    const dim3 gridH(HF / 128,  (NN + 127) / 128);
    const dim3 gridWc(1, 4);
    const int gatherBlocks = (NN * 32 + 255) / 256;

    cudaStream_t chain[2] = {(cudaStream_t)0, g_hx.s1};
    cudaStream_t sideS[2] = {g_hx.s2, g_hx.s3};
    cudaEvent_t  csrE[2]  = {g_hx.ec0, g_hx.ec1};
    cudaEvent_t  prepE[2] = {g_hx.ep0, g_hx.ep1};

    // fork from the capture stream
    cudaEventRecord(g_hx.e0, chain[0]);
    cudaStreamWaitEvent(chain[1], g_hx.e0, 0);
    cudaStreamWaitEvent(sideS[0], g_hx.e0, 0);
    cudaStreamWaitEvent(sideS[1], g_hx.e0, 0);

    // side streams: prep + weight-combine + CSR build (+ fa for type 1)
    for (int t = 0; t < 2; t++) {
        cudaStream_t s = sideS[t];
        pack_bf16_k<<<(NN * 64 + 255) / 256, 256, 0, s>>>(embP[t], hemb[t], NN * 64);
        pack_bf16_k<<<(128 * 128 + 255) / 256, 256, 0, s>>>(Wpk[t], W[t], 128 * 128);
        repack_pack<<<(512 * 128 + 255) / 256, 256, 0, s>>>(Bp0[t], gw[t][0], FUNI);
        gemm_bf16<<<gridWc, 256, SMEM_GEMM, s>>>(Bp0[t], Wpk[t], Wc[t], 512, 256, 128,
                                                 nullptr, nullptr, nullptr, nullptr);
        repack_pack<<<(512 * 256 + 255) / 256, 256, 0, s>>>(Bp1[t], gw[t][1], HF);
        if (t == 1)
            fa_kernel<<<1, 64, 0, s>>>(hemb[1], W[1], aw1);
        cudaEventRecord(prepE[t], s);

        const int* src = edge[t];
        const int* trg = edge[t] + EE;
        zero_cnt<<<(NN + 255) / 256, 256, 0, s>>>(t);
        hist_kernel<<<(EE + 255) / 256, 256, 0, s>>>(trg, t);
        scan_kernel<<<1, 1024, 0, s>>>(t);
        fill_kernel<<<(EE + 255) / 256, 256, 0, s>>>(src, trg, t);
        cudaEventRecord(csrE[t], s);
    }

    for (int t = 0; t < 2; t++) {
        cudaStream_t s = chain[t];
        cudaStreamWaitEvent(s, prepE[t], 0);

        // layer 0: emb @ Wc (K=128), fp8 hp + fused s/t
        gemm_bf16<<<gridH, 256, SMEM_GEMM, s>>>(embP[t], Wc[t], hp[t], NN, 128, HF,
                                                gasrc[t][0], gatrg[t][0], sArr[t], tArr[t]);
        cudaStreamWaitEvent(s, csrE[t], 0);
        gather_agg<<<gatherBlocks, 256, 0, s>>>(csr[t], rowptr[t], hp[t], sArr[t], tArr[t], x0[t], 1);

        // layer 1 (K=512), fp8 hp + fused s/t; gather emits head-means
        gemm_bf16<<<gridH, 256, SMEM_GEMM, s>>>(x0[t], Bp1[t], hp[t], NN, HF, HF,
                                                gasrc[t][1], gatrg[t][1], sArr[t], tArr[t]);
        gather_agg<<<gatherBlocks, 256, 0, s>>>(csr[t], rowptr[t], hp[t], sArr[t], tArr[t], meanArr[t], 2);
    }

    // join
    cudaEventRecord(g_hx.e1, chain[1]);
    cudaStreamWaitEvent(chain[0], g_hx.e1, 0);

    final_kernel<<<NN, 64, 0, chain[0]>>>(aw2, am, fcw, fcb, (float*)d_out);
}